// round 7
// baseline (speedup 1.0000x reference)
#include <cuda_runtime.h>
#include <cuda_bf16.h>
#include <cstdint>
#include <cstddef>

// Problem constants
#define NROWS   65536
#define VDIM    1024
#define DDIM    256
#define M_TILE  64
#define NCTAS   (NROWS / M_TILE)     // 1024
#define NTHREADS 256
#define KCH     64
#define NCHUNK  (VDIM / KCH)         // 16
#define ROWB    144                  // bytes per smem tile row (64 bf16 + 8 pad)
#define A_TILE  (M_TILE * ROWB)      // 9216
#define B_TILE  (DDIM * ROWB)        // 36864
#define SMEM_BYTES (2 * (A_TILE + B_TILE))   // 92160 -> 2 CTAs/SM

// Static scratch: codebook transposed+converted to bf16, [D][V]
__device__ __nv_bfloat16 g_cbT[DDIM * VDIM];
__device__ int g_tgt64;

// ---------------------------------------------------------------------------
// Prep: transpose codebook fp32 [V][D] -> bf16 [D][V]; zero out; dtype sniff.
// ---------------------------------------------------------------------------
__global__ void prep_kernel(const float* __restrict__ cb,
                            const void*  __restrict__ tgt,
                            float* __restrict__ out) {
    __shared__ float tile[32][33];
    int v0 = blockIdx.x * 32;
    int d0 = blockIdx.y * 32;
    int tx = threadIdx.x, ty = threadIdx.y;

    #pragma unroll
    for (int i = 0; i < 4; i++) {
        int v = ty + i * 8;
        tile[v][tx] = cb[(size_t)(v0 + v) * DDIM + d0 + tx];
    }
    __syncthreads();
    #pragma unroll
    for (int i = 0; i < 4; i++) {
        int d = ty + i * 8;
        g_cbT[(size_t)(d0 + d) * VDIM + v0 + tx] = __float2bfloat16(tile[tx][d]);
    }

    if (blockIdx.x == 0 && blockIdx.y == 0 && tx == 0 && ty == 0) {
        const int* t = (const int*)tgt;
        int is64 = 1;
        for (int i = 0; i < 256; i++) {
            if (t[2 * i + 1] != 0) { is64 = 0; break; }
        }
        g_tgt64 = is64;
        out[0] = 0.0f;
    }
}

// ---------------------------------------------------------------------------
// Helpers
// ---------------------------------------------------------------------------
__device__ __forceinline__ uint32_t smem_u32(const void* p) {
    uint32_t a;
    asm("{ .reg .u64 t; cvta.to.shared.u64 t, %1; cvt.u32.u64 %0, t; }" : "=r"(a) : "l"(p));
    return a;
}

__device__ __forceinline__ void cp16(uint32_t dst_smem, const void* src_gmem) {
    asm volatile("cp.async.cg.shared.global [%0], [%1], 16;" :: "r"(dst_smem), "l"(src_gmem));
}

__device__ __forceinline__ void ldsm_x4(uint32_t (&r)[4], uint32_t addr) {
    asm volatile("ldmatrix.sync.aligned.m8n8.x4.shared.b16 {%0,%1,%2,%3}, [%4];"
                 : "=r"(r[0]), "=r"(r[1]), "=r"(r[2]), "=r"(r[3]) : "r"(addr));
}

__device__ __forceinline__ void mma16816(float (&c)[4], const uint32_t (&a)[4],
                                         uint32_t b0, uint32_t b1) {
    asm volatile(
        "mma.sync.aligned.m16n8k16.row.col.f32.bf16.bf16.f32 "
        "{%0,%1,%2,%3}, {%4,%5,%6,%7}, {%8,%9}, {%0,%1,%2,%3};"
        : "+f"(c[0]), "+f"(c[1]), "+f"(c[2]), "+f"(c[3])
        : "r"(a[0]), "r"(a[1]), "r"(a[2]), "r"(a[3]), "r"(b0), "r"(b1));
}

// ---------------------------------------------------------------------------
// Fused streaming kernel with intra-chunk software pipelining:
// per chunk kc: bar -> B(kc+1) cp.async -> MMA(kc) interleaved with
// exp(kc+1)->A[buf^1] and logits(kc+2) prefetch -> bar.
// Grid: 1024 CTAs x 256 threads (8 warps, 2M x 4N). 2 CTAs per SM.
// ---------------------------------------------------------------------------
__global__ void __launch_bounds__(NTHREADS, 2)
loss_kernel(const float* __restrict__ logits,
            const void*  __restrict__ tgt,
            const float* __restrict__ cb,
            float* __restrict__ out) {
    extern __shared__ char smem[];
    char* Ash = smem;                      // 2 x [64][144B]
    char* Bsh = smem + 2 * A_TILE;         // 2 x [256][144B]
    __shared__ float rowinv[M_TILE];
    __shared__ float sred[8];

    const int tid  = threadIdx.x;
    const int lane = tid & 31;
    const int wid  = tid >> 5;
    const int warp_m = wid & 1;    // 0..1
    const int warp_n = wid >> 1;   // 0..3

    // Per-thread logits slice: row = tid>>2 (0..63), quarter q = tid&3.
    const int row = tid >> 2;
    const int q   = tid & 3;
    const float4* src4 = (const float4*)(logits + (size_t)blockIdx.x * M_TILE * VDIM);
    const size_t rb4 = (size_t)row * (VDIM / 4);

    const uint32_t a_smem = smem_u32(Ash);
    const uint32_t b_smem = smem_u32(Bsh);

    // ldmatrix source offsets (within a buffer)
    const uint32_t a_lds_off =
        (uint32_t)((warp_m * 32 + (lane & 15)) * ROWB + ((lane >> 4) << 4));
    const uint32_t b_lds_off =
        (uint32_t)(((lane & 7) + ((lane >> 4) << 3)) * ROWB + (((lane >> 3) & 1) << 4));

    // A store target for this thread (within a buffer)
    char* const a_sts = Ash + row * ROWB + q * 32;

    float rs = 0.0f;

    // --- Prologue --------------------------------------------------------
    // Issue B chunk 0 copy.
    #pragma unroll
    for (int i = 0; i < 8; i++) {
        int idx = tid + i * NTHREADS;     // 0..2047
        int n   = idx >> 3;
        int kv  = idx & 7;
        cp16(b_smem + n * ROWB + kv * 16, g_cbT + (size_t)n * VDIM + kv * 8);
    }
    asm volatile("cp.async.commit_group;" ::: "memory");

    // Load chunk 0, exp into A[0]; prefetch chunk 1.
    float4 v[2][4];
    #pragma unroll
    for (int j = 0; j < 4; j++) v[0][j] = src4[rb4 + q * 4 + j];
    #pragma unroll
    for (int j = 0; j < 4; j++) {
        float e0 = __expf(v[0][j].x), e1 = __expf(v[0][j].y);
        float e2 = __expf(v[0][j].z), e3 = __expf(v[0][j].w);
        rs += (e0 + e1) + (e2 + e3);
        __nv_bfloat162 h01 = __floats2bfloat162_rn(e0, e1);
        __nv_bfloat162 h23 = __floats2bfloat162_rn(e2, e3);
        uint2 pk;
        pk.x = *(unsigned*)&h01;
        pk.y = *(unsigned*)&h23;
        *(uint2*)(a_sts + j * 8) = pk;
    }
    #pragma unroll
    for (int j = 0; j < 4; j++) v[1][j] = src4[rb4 + 16 + q * 4 + j];

    asm volatile("cp.async.wait_group 0;" ::: "memory");
    __syncthreads();

    float acc[2][8][4];
    #pragma unroll
    for (int mi = 0; mi < 2; mi++)
        #pragma unroll
        for (int nf = 0; nf < 8; nf++)
            #pragma unroll
            for (int x = 0; x < 4; x++) acc[mi][nf][x] = 0.0f;

    // --- Main pipelined loop ----------------------------------------------
    #pragma unroll 1
    for (int kc = 0; kc < NCHUNK; kc++) {
        const int buf = kc & 1;
        const int nbuf = buf ^ 1;

        // Issue B copy for chunk kc+1 into the other buffer.
        if (kc + 1 < NCHUNK) {
            uint32_t bdst = b_smem + nbuf * B_TILE;
            #pragma unroll
            for (int i = 0; i < 8; i++) {
                int idx = tid + i * NTHREADS;
                int n   = idx >> 3;
                int kv  = idx & 7;
                cp16(bdst + n * ROWB + kv * 16,
                     g_cbT + (size_t)n * VDIM + (kc + 1) * KCH + kv * 8);
            }
            asm volatile("cp.async.commit_group;" ::: "memory");
            asm volatile("cp.async.wait_group 1;" ::: "memory");  // B[kc] done
        } else {
            asm volatile("cp.async.wait_group 0;" ::: "memory");
        }

        const uint32_t a_buf = a_smem + buf * A_TILE + a_lds_off;
        const uint32_t b_buf = b_smem + buf * B_TILE + b_lds_off;
        char* const a_next = a_sts + nbuf * A_TILE;   // exp(kc+1) target
        const bool do_exp = (kc + 1 < NCHUNK);
        const bool do_pref = (kc + 2 < NCHUNK);

        #pragma unroll
        for (int ks = 0; ks < 4; ks++) {
            uint32_t afr[2][4];
            ldsm_x4(afr[0], a_buf + ks * 32);
            ldsm_x4(afr[1], a_buf + 16 * ROWB + ks * 32);
            #pragma unroll
            for (int nb = 0; nb < 4; nb++) {
                uint32_t bfr[4];
                ldsm_x4(bfr, b_buf + (warp_n * 64 + nb * 16) * ROWB + ks * 32);
                mma16816(acc[0][nb * 2 + 0], afr[0], bfr[0], bfr[1]);
                mma16816(acc[0][nb * 2 + 1], afr[0], bfr[2], bfr[3]);
                mma16816(acc[1][nb * 2 + 0], afr[1], bfr[0], bfr[1]);
                mma16816(acc[1][nb * 2 + 1], afr[1], bfr[2], bfr[3]);
            }

            // Interleaved: exp one quarter of chunk kc+1 into A[nbuf],
            // and prefetch one quarter of chunk kc+2.
            if (do_exp) {
                float4 vv = v[nbuf][ks];
                float e0 = __expf(vv.x), e1 = __expf(vv.y);
                float e2 = __expf(vv.z), e3 = __expf(vv.w);
                rs += (e0 + e1) + (e2 + e3);
                __nv_bfloat162 h01 = __floats2bfloat162_rn(e0, e1);
                __nv_bfloat162 h23 = __floats2bfloat162_rn(e2, e3);
                uint2 pk;
                pk.x = *(unsigned*)&h01;
                pk.y = *(unsigned*)&h23;
                *(uint2*)(a_next + ks * 8) = pk;
                if (do_pref)
                    v[buf][ks] = src4[rb4 + (size_t)(kc + 2) * 16 + q * 4 + ks];
            }
        }

        __syncthreads();
    }

    // Row-sum reduce across the 4 threads sharing a row.
    {
        float s = rs;
        s += __shfl_xor_sync(0xffffffffu, s, 1);
        s += __shfl_xor_sync(0xffffffffu, s, 2);
        if (q == 0) rowinv[row] = 1.0f / s;
    }
    __syncthreads();

    // Epilogue: pred = acc * rowinv; loss += (pred - cb[target])^2
    const int is64 = g_tgt64;
    const long long* t64 = (const long long*)tgt;
    const int*       t32 = (const int*)tgt;

    float lsum = 0.0f;
    #pragma unroll
    for (int mi = 0; mi < 2; mi++) {
        int lr0 = warp_m * 32 + mi * 16 + (lane >> 2);
        int lr1 = lr0 + 8;
        int r0 = blockIdx.x * M_TILE + lr0;
        int r1 = blockIdx.x * M_TILE + lr1;
        float inv0 = rowinv[lr0];
        float inv1 = rowinv[lr1];
        int tg0 = is64 ? (int)t64[r0] : t32[r0];
        int tg1 = is64 ? (int)t64[r1] : t32[r1];
        const float* cb0 = cb + (size_t)tg0 * DDIM;
        const float* cb1 = cb + (size_t)tg1 * DDIM;
        #pragma unroll
        for (int nf = 0; nf < 8; nf++) {
            int col = warp_n * 64 + nf * 8 + (lane & 3) * 2;
            float2 g0 = *(const float2*)(cb0 + col);
            float2 g1 = *(const float2*)(cb1 + col);
            float d0 = acc[mi][nf][0] * inv0 - g0.x;
            float d1 = acc[mi][nf][1] * inv0 - g0.y;
            float d2 = acc[mi][nf][2] * inv1 - g1.x;
            float d3 = acc[mi][nf][3] * inv1 - g1.y;
            lsum += d0 * d0 + d1 * d1 + d2 * d2 + d3 * d3;
        }
    }
    #pragma unroll
    for (int off = 16; off > 0; off >>= 1)
        lsum += __shfl_xor_sync(0xffffffffu, lsum, off);

    if (lane == 0) sred[wid] = lsum;
    __syncthreads();
    if (tid == 0) {
        float tot = 0.0f;
        #pragma unroll
        for (int i = 0; i < 8; i++) tot += sred[i];
        atomicAdd(out, tot * (1.0f / ((float)NROWS * (float)DDIM)));
    }
}

// ---------------------------------------------------------------------------
// Launch
// ---------------------------------------------------------------------------
extern "C" void kernel_launch(void* const* d_in, const int* in_sizes, int n_in,
                              void* d_out, int out_size) {
    const float* logits = nullptr;
    const void*  tgt    = nullptr;
    const float* cb     = nullptr;
    for (int i = 0; i < n_in; i++) {
        if (in_sizes[i] == NROWS * VDIM)      logits = (const float*)d_in[i];
        else if (in_sizes[i] == NROWS)        tgt    = d_in[i];
        else if (in_sizes[i] == VDIM * DDIM)  cb     = (const float*)d_in[i];
    }
    float* out = (float*)d_out;

    cudaFuncSetAttribute(loss_kernel,
                         cudaFuncAttributeMaxDynamicSharedMemorySize, SMEM_BYTES);

    dim3 pgrid(VDIM / 32, DDIM / 32);
    dim3 pblk(32, 8);
    prep_kernel<<<pgrid, pblk>>>(cb, tgt, out);

    loss_kernel<<<NCTAS, NTHREADS, SMEM_BYTES>>>(logits, tgt, cb, out);
}

// round 8
// speedup vs baseline: 1.2697x; 1.2697x over previous
#include <cuda_runtime.h>
#include <cuda_bf16.h>
#include <cstdint>
#include <cstddef>

// Problem constants
#define NROWS   65536
#define VDIM    1024
#define DDIM    256
#define M_TILE  64
#define NCTAS   (NROWS / M_TILE)     // 1024
#define NTHREADS 128                 // 4 warps, each M64 x N64
#define KCH     64
#define NCHUNK  (VDIM / KCH)         // 16
#define ROWB    128                  // exact 128B rows + XOR swizzle (no pad)
#define A_TILE  (M_TILE * ROWB)      // 8192
#define B_TILE  (DDIM * ROWB)        // 32768
#define SMEM_BYTES (2 * (A_TILE + B_TILE))   // 81920 -> 2 CTAs/SM

// Static scratch: codebook transposed+converted to bf16, [D][V]
__device__ __nv_bfloat16 g_cbT[DDIM * VDIM];
__device__ int g_tgt64;

// ---------------------------------------------------------------------------
// Prep: transpose codebook fp32 [V][D] -> bf16 [D][V]; zero out; dtype sniff.
// ---------------------------------------------------------------------------
__global__ void prep_kernel(const float* __restrict__ cb,
                            const void*  __restrict__ tgt,
                            float* __restrict__ out) {
    __shared__ float tile[32][33];
    int v0 = blockIdx.x * 32;
    int d0 = blockIdx.y * 32;
    int tx = threadIdx.x, ty = threadIdx.y;

    #pragma unroll
    for (int i = 0; i < 4; i++) {
        int v = ty + i * 8;
        tile[v][tx] = cb[(size_t)(v0 + v) * DDIM + d0 + tx];
    }
    __syncthreads();
    #pragma unroll
    for (int i = 0; i < 4; i++) {
        int d = ty + i * 8;
        g_cbT[(size_t)(d0 + d) * VDIM + v0 + tx] = __float2bfloat16(tile[tx][d]);
    }

    if (blockIdx.x == 0 && blockIdx.y == 0 && tx == 0 && ty == 0) {
        const int* t = (const int*)tgt;
        int is64 = 1;
        for (int i = 0; i < 256; i++) {
            if (t[2 * i + 1] != 0) { is64 = 0; break; }
        }
        g_tgt64 = is64;
        out[0] = 0.0f;
    }
}

// ---------------------------------------------------------------------------
// Helpers
// ---------------------------------------------------------------------------
__device__ __forceinline__ uint32_t smem_u32(const void* p) {
    uint32_t a;
    asm("{ .reg .u64 t; cvta.to.shared.u64 t, %1; cvt.u32.u64 %0, t; }" : "=r"(a) : "l"(p));
    return a;
}

__device__ __forceinline__ void cp16(uint32_t dst_smem, const void* src_gmem) {
    asm volatile("cp.async.cg.shared.global [%0], [%1], 16;" :: "r"(dst_smem), "l"(src_gmem));
}

__device__ __forceinline__ void ldsm_x4(uint32_t (&r)[4], uint32_t addr) {
    asm volatile("ldmatrix.sync.aligned.m8n8.x4.shared.b16 {%0,%1,%2,%3}, [%4];"
                 : "=r"(r[0]), "=r"(r[1]), "=r"(r[2]), "=r"(r[3]) : "r"(addr));
}

__device__ __forceinline__ void mma16816(float (&c)[4], const uint32_t (&a)[4],
                                         uint32_t b0, uint32_t b1) {
    asm volatile(
        "mma.sync.aligned.m16n8k16.row.col.f32.bf16.bf16.f32 "
        "{%0,%1,%2,%3}, {%4,%5,%6,%7}, {%8,%9}, {%0,%1,%2,%3};"
        : "+f"(c[0]), "+f"(c[1]), "+f"(c[2]), "+f"(c[3])
        : "r"(a[0]), "r"(a[1]), "r"(a[2]), "r"(a[3]), "r"(b0), "r"(b1));
}

// XOR-SW128 address within a tile of 128B rows: col bits [4:7) XOR row bits [0:3)
__device__ __forceinline__ uint32_t swz(uint32_t row, uint32_t col) {
    return row * 128u + (col ^ ((row & 7u) << 4));
}

// ---------------------------------------------------------------------------
// Fused streaming kernel, big warp tiles:
// 4 warps, each M64 x N64 (acc 128 regs). CTA tile M64 x N256.
// Per chunk: prefetch logits(kc+1) -> exp(kc)->A[buf] -> bar -> B(kc+1)
// cp.async -> MMA(kc).
// ---------------------------------------------------------------------------
__global__ void __launch_bounds__(NTHREADS, 2)
loss_kernel(const float* __restrict__ logits,
            const void*  __restrict__ tgt,
            const float* __restrict__ cb,
            float* __restrict__ out) {
    extern __shared__ char smem[];
    char* Ash = smem;                      // 2 x [64][128B] swizzled
    char* Bsh = smem + 2 * A_TILE;         // 2 x [256][128B] swizzled
    __shared__ float rowinv[M_TILE];
    __shared__ float sred[4];

    const int tid  = threadIdx.x;
    const int lane = tid & 31;
    const int wid  = tid >> 5;             // warp_n = wid (0..3)

    // Logits mapping: row = tid>>1 (0..63), half = tid&1 (k 0..31 / 32..63)
    const int row  = tid >> 1;
    const int half = tid & 1;
    const float4* src4 = (const float4*)(logits + (size_t)blockIdx.x * M_TILE * VDIM);
    const size_t rb4 = (size_t)row * (VDIM / 4);

    const uint32_t a_smem = smem_u32(Ash);
    const uint32_t b_smem = smem_u32(Bsh);

    // A store: 4 x 16B at cols half*64 + i*16 (swizzled), row fixed.
    const uint32_t a_sts_base = a_smem + row * 128u;
    const uint32_t a_xor = (uint32_t)((row & 7) << 4);

    // ldmatrix lane geometry
    const uint32_t a_r  = (uint32_t)(lane & 15);          // + mi*16
    const uint32_t a_c0 = (uint32_t)((lane >> 4) << 4);   // + ks*32
    const uint32_t b_r  = (uint32_t)((lane & 7) + ((lane >> 4) << 3));  // + wid*64 + nb*16
    const uint32_t b_c0 = (uint32_t)(((lane >> 3) & 1) << 4);           // + ks*32

    float rs = 0.0f;

    // --- Prologue: B chunk 0 copy + logits chunk 0 load --------------------
    #pragma unroll
    for (int i = 0; i < 16; i++) {
        int idx = tid + i * NTHREADS;     // 0..2047
        int n   = idx >> 3;
        int kv  = idx & 7;
        cp16(b_smem + swz(n, kv * 16), g_cbT + (size_t)n * VDIM + kv * 8);
    }
    asm volatile("cp.async.commit_group;" ::: "memory");

    float4 cur[8], nxt[8];
    #pragma unroll
    for (int j = 0; j < 8; j++) cur[j] = src4[rb4 + half * 8 + j];

    float acc[4][8][4];
    #pragma unroll
    for (int mi = 0; mi < 4; mi++)
        #pragma unroll
        for (int nf = 0; nf < 8; nf++)
            #pragma unroll
            for (int x = 0; x < 4; x++) acc[mi][nf][x] = 0.0f;

    // --- Main loop ----------------------------------------------------------
    #pragma unroll 1
    for (int kc = 0; kc < NCHUNK; kc++) {
        const int buf = kc & 1;

        // Prefetch next logits chunk (8 independent LDGs, MLP 8).
        if (kc + 1 < NCHUNK) {
            #pragma unroll
            for (int j = 0; j < 8; j++)
                nxt[j] = src4[rb4 + (size_t)(kc + 1) * 16 + half * 8 + j];
        }

        // exp + rowsum + bf16 -> A[buf] (4 x 16B swizzled stores).
        {
            uint32_t abase = a_sts_base + buf * (uint32_t)A_TILE;
            #pragma unroll
            for (int i = 0; i < 4; i++) {
                float4 v0 = cur[2 * i];
                float4 v1 = cur[2 * i + 1];
                float e0 = __expf(v0.x), e1 = __expf(v0.y);
                float e2 = __expf(v0.z), e3 = __expf(v0.w);
                float e4 = __expf(v1.x), e5 = __expf(v1.y);
                float e6 = __expf(v1.z), e7 = __expf(v1.w);
                rs += ((e0 + e1) + (e2 + e3)) + ((e4 + e5) + (e6 + e7));
                __nv_bfloat162 h0 = __floats2bfloat162_rn(e0, e1);
                __nv_bfloat162 h1 = __floats2bfloat162_rn(e2, e3);
                __nv_bfloat162 h2 = __floats2bfloat162_rn(e4, e5);
                __nv_bfloat162 h3 = __floats2bfloat162_rn(e6, e7);
                uint4 pk;
                pk.x = *(unsigned*)&h0;
                pk.y = *(unsigned*)&h1;
                pk.z = *(unsigned*)&h2;
                pk.w = *(unsigned*)&h3;
                uint32_t col = (uint32_t)(half * 64 + i * 16) ^ a_xor;
                asm volatile("st.shared.v4.b32 [%0], {%1,%2,%3,%4};"
                             :: "r"(abase + col), "r"(pk.x), "r"(pk.y), "r"(pk.z), "r"(pk.w));
            }
        }

        // B[kc] resident, A stores visible.
        asm volatile("cp.async.wait_group 0;" ::: "memory");
        __syncthreads();

        // Issue B chunk kc+1 into the other buffer (readers finished).
        if (kc + 1 < NCHUNK) {
            uint32_t bdst = b_smem + (buf ^ 1) * (uint32_t)B_TILE;
            #pragma unroll
            for (int i = 0; i < 16; i++) {
                int idx = tid + i * NTHREADS;
                int n   = idx >> 3;
                int kv  = idx & 7;
                cp16(bdst + swz(n, kv * 16),
                     g_cbT + (size_t)n * VDIM + (kc + 1) * KCH + kv * 8);
            }
            asm volatile("cp.async.commit_group;" ::: "memory");
        }

        // MMA: A[64x64] x B[64x256], warp slice N64.
        const uint32_t a_buf = a_smem + buf * (uint32_t)A_TILE;
        const uint32_t b_buf = b_smem + buf * (uint32_t)B_TILE;

        #pragma unroll
        for (int ks = 0; ks < 4; ks++) {
            uint32_t afr[4][4];
            #pragma unroll
            for (int mi = 0; mi < 4; mi++)
                ldsm_x4(afr[mi], a_buf + swz(mi * 16 + a_r, ks * 32 + a_c0));
            #pragma unroll
            for (int nb = 0; nb < 4; nb++) {
                uint32_t bfr[4];
                ldsm_x4(bfr, b_buf + swz(wid * 64 + nb * 16 + b_r, ks * 32 + b_c0));
                #pragma unroll
                for (int mi = 0; mi < 4; mi++) {
                    mma16816(acc[mi][nb * 2 + 0], afr[mi], bfr[0], bfr[1]);
                    mma16816(acc[mi][nb * 2 + 1], afr[mi], bfr[2], bfr[3]);
                }
            }
        }

        #pragma unroll
        for (int j = 0; j < 8; j++) cur[j] = nxt[j];
    }

    // Row-sum reduce: pair (tid, tid^1) share a row.
    {
        float s = rs + __shfl_xor_sync(0xffffffffu, rs, 1);
        if (half == 0) rowinv[row] = 1.0f / s;
    }
    __syncthreads();

    // Epilogue: pred = acc * rowinv; loss += (pred - cb[target])^2
    const int is64 = g_tgt64;
    const long long* t64 = (const long long*)tgt;
    const int*       t32 = (const int*)tgt;

    float lsum = 0.0f;
    #pragma unroll
    for (int mi = 0; mi < 4; mi++) {
        int lr0 = mi * 16 + (lane >> 2);
        int lr1 = lr0 + 8;
        int r0 = blockIdx.x * M_TILE + lr0;
        int r1 = blockIdx.x * M_TILE + lr1;
        float inv0 = rowinv[lr0];
        float inv1 = rowinv[lr1];
        int tg0 = is64 ? (int)t64[r0] : t32[r0];
        int tg1 = is64 ? (int)t64[r1] : t32[r1];
        const float* cb0 = cb + (size_t)tg0 * DDIM;
        const float* cb1 = cb + (size_t)tg1 * DDIM;
        #pragma unroll
        for (int nf = 0; nf < 8; nf++) {
            int col = wid * 64 + nf * 8 + (lane & 3) * 2;
            float2 g0 = *(const float2*)(cb0 + col);
            float2 g1 = *(const float2*)(cb1 + col);
            float d0 = acc[mi][nf][0] * inv0 - g0.x;
            float d1 = acc[mi][nf][1] * inv0 - g0.y;
            float d2 = acc[mi][nf][2] * inv1 - g1.x;
            float d3 = acc[mi][nf][3] * inv1 - g1.y;
            lsum += d0 * d0 + d1 * d1 + d2 * d2 + d3 * d3;
        }
    }
    #pragma unroll
    for (int off = 16; off > 0; off >>= 1)
        lsum += __shfl_xor_sync(0xffffffffu, lsum, off);

    if (lane == 0) sred[wid] = lsum;
    __syncthreads();
    if (tid == 0) {
        float tot = sred[0] + sred[1] + sred[2] + sred[3];
        atomicAdd(out, tot * (1.0f / ((float)NROWS * (float)DDIM)));
    }
}

// ---------------------------------------------------------------------------
// Launch
// ---------------------------------------------------------------------------
extern "C" void kernel_launch(void* const* d_in, const int* in_sizes, int n_in,
                              void* d_out, int out_size) {
    const float* logits = nullptr;
    const void*  tgt    = nullptr;
    const float* cb     = nullptr;
    for (int i = 0; i < n_in; i++) {
        if (in_sizes[i] == NROWS * VDIM)      logits = (const float*)d_in[i];
        else if (in_sizes[i] == NROWS)        tgt    = d_in[i];
        else if (in_sizes[i] == VDIM * DDIM)  cb     = (const float*)d_in[i];
    }
    float* out = (float*)d_out;

    cudaFuncSetAttribute(loss_kernel,
                         cudaFuncAttributeMaxDynamicSharedMemorySize, SMEM_BYTES);

    dim3 pgrid(VDIM / 32, DDIM / 32);
    dim3 pblk(32, 8);
    prep_kernel<<<pgrid, pblk>>>(cb, tgt, out);

    loss_kernel<<<NCTAS, NTHREADS, SMEM_BYTES>>>(logits, tgt, cb, out);
}

// round 9
// speedup vs baseline: 1.5039x; 1.1845x over previous
#include <cuda_runtime.h>
#include <cuda_bf16.h>
#include <cstdint>
#include <cstddef>

// Problem constants
#define NROWS   65536
#define VDIM    1024
#define DDIM    256
#define M_TILE  64
#define NCTAS   (NROWS / M_TILE)     // 1024
#define NTHREADS 256
#define KCH     64
#define NCHUNK  (VDIM / KCH)         // 16
#define ASTRIDE 72                   // bf16 elems per A smem row (144B, conflict-free)
#define BSTRIDE 72
#define A_ELEMS (M_TILE * ASTRIDE)   // 64*72
#define B_ELEMS (DDIM * BSTRIDE)     // 256*72
#define SMEM_BYTES ((2 * A_ELEMS + 2 * B_ELEMS) * 2)   // 92160 B -> 2 CTAs/SM
#define ROWB    (ASTRIDE * 2)        // 144 bytes

// Static scratch: codebook transposed+converted to bf16, [D][V]
__device__ __nv_bfloat16 g_cbT[DDIM * VDIM];
__device__ int g_tgt64;

// ---------------------------------------------------------------------------
// Prep: transpose codebook fp32 [V][D] -> bf16 [D][V]; zero out; dtype sniff.
// ---------------------------------------------------------------------------
__global__ void prep_kernel(const float* __restrict__ cb,
                            const void*  __restrict__ tgt,
                            float* __restrict__ out) {
    __shared__ float tile[32][33];
    int v0 = blockIdx.x * 32;
    int d0 = blockIdx.y * 32;
    int tx = threadIdx.x, ty = threadIdx.y;

    #pragma unroll
    for (int i = 0; i < 4; i++) {
        int v = ty + i * 8;
        tile[v][tx] = cb[(size_t)(v0 + v) * DDIM + d0 + tx];
    }
    __syncthreads();
    #pragma unroll
    for (int i = 0; i < 4; i++) {
        int d = ty + i * 8;
        g_cbT[(size_t)(d0 + d) * VDIM + v0 + tx] = __float2bfloat16(tile[tx][d]);
    }

    if (blockIdx.x == 0 && blockIdx.y == 0 && tx == 0 && ty == 0) {
        const int* t = (const int*)tgt;
        int is64 = 1;
        for (int i = 0; i < 256; i++) {
            if (t[2 * i + 1] != 0) { is64 = 0; break; }
        }
        g_tgt64 = is64;
        out[0] = 0.0f;
    }
}

// ---------------------------------------------------------------------------
// Helpers
// ---------------------------------------------------------------------------
__device__ __forceinline__ uint32_t smem_u32(const void* p) {
    uint32_t a;
    asm("{ .reg .u64 t; cvta.to.shared.u64 t, %1; cvt.u32.u64 %0, t; }" : "=r"(a) : "l"(p));
    return a;
}

__device__ __forceinline__ void cp16(uint32_t dst_smem, const void* src_gmem) {
    asm volatile("cp.async.cg.shared.global [%0], [%1], 16;" :: "r"(dst_smem), "l"(src_gmem));
}

__device__ __forceinline__ void ldsm_x4(uint32_t (&r)[4], uint32_t addr) {
    asm volatile("ldmatrix.sync.aligned.m8n8.x4.shared.b16 {%0,%1,%2,%3}, [%4];"
                 : "=r"(r[0]), "=r"(r[1]), "=r"(r[2]), "=r"(r[3]) : "r"(addr));
}

__device__ __forceinline__ void mma16816(float (&c)[4], const uint32_t (&a)[4],
                                         uint32_t b0, uint32_t b1) {
    asm volatile(
        "mma.sync.aligned.m16n8k16.row.col.f32.bf16.bf16.f32 "
        "{%0,%1,%2,%3}, {%4,%5,%6,%7}, {%8,%9}, {%0,%1,%2,%3};"
        : "+f"(c[0]), "+f"(c[1]), "+f"(c[2]), "+f"(c[3])
        : "r"(a[0]), "r"(a[1]), "r"(a[2]), "r"(a[3]), "r"(b0), "r"(b1));
}

// ---------------------------------------------------------------------------
// Fused streaming kernel (R4 base + pipelined B-fragment LDSM):
// exp(logits) chunks -> mma.sync GEMM (deferred softmax normalization)
// -> squared-error reduce.
// Grid: 1024 CTAs x 256 threads (8 warps, 2M x 4N). 2 CTAs per SM.
// ---------------------------------------------------------------------------
__global__ void __launch_bounds__(NTHREADS, 2)
loss_kernel(const float* __restrict__ logits,
            const void*  __restrict__ tgt,
            const float* __restrict__ cb,
            float* __restrict__ out) {
    extern __shared__ char smem[];
    char* Ash = smem;                      // 2 x [64][144B]
    char* Bsh = smem + 2 * A_ELEMS * 2;    // 2 x [256][144B]
    __shared__ float rowinv[M_TILE];
    __shared__ float sred[8];

    const int tid  = threadIdx.x;
    const int lane = tid & 31;
    const int wid  = tid >> 5;
    const int warp_m = wid & 1;    // 0..1
    const int warp_n = wid >> 1;   // 0..3

    // Per-thread logits slice: row = tid>>2 (0..63), quarter q = tid&3.
    const int row = tid >> 2;
    const int q   = tid & 3;
    const float4* src4 = (const float4*)(logits + (size_t)blockIdx.x * M_TILE * VDIM);
    const size_t rb4 = (size_t)row * (VDIM / 4);

    const uint32_t a_smem = smem_u32(Ash);
    const uint32_t b_smem = smem_u32(Bsh);

    // ldmatrix source addresses (within a buffer)
    const uint32_t a_lds_off =
        (uint32_t)((warp_m * 32 + (lane & 15)) * ROWB + ((lane >> 4) << 4));
    const uint32_t b_lds_off =
        (uint32_t)((warp_n * 64 + (lane & 7) + ((lane >> 4) << 3)) * ROWB +
                   (((lane >> 3) & 1) << 4));

    // A store target for this thread (within a buffer): 2 x 16B
    char* const a_sts = Ash + row * ROWB + q * 32;

    float rs = 0.0f;

    // --- Prologue: B chunk 0 copy + logits chunk 0 load --------------------
    #pragma unroll
    for (int i = 0; i < 8; i++) {
        int idx = tid + i * NTHREADS;     // 0..2047
        int n   = idx >> 3;
        int kv  = idx & 7;
        cp16(b_smem + n * ROWB + kv * 16, g_cbT + (size_t)n * VDIM + kv * 8);
    }
    asm volatile("cp.async.commit_group;" ::: "memory");

    float4 cur[4], nxt[4];
    #pragma unroll
    for (int j = 0; j < 4; j++) cur[j] = __ldcs(&src4[rb4 + q * 4 + j]);

    float acc[2][8][4];
    #pragma unroll
    for (int mi = 0; mi < 2; mi++)
        #pragma unroll
        for (int nf = 0; nf < 8; nf++)
            #pragma unroll
            for (int x = 0; x < 4; x++) acc[mi][nf][x] = 0.0f;

    // --- Main loop ----------------------------------------------------------
    #pragma unroll 1
    for (int kc = 0; kc < NCHUNK; kc++) {
        const int buf = kc & 1;

        // Prefetch next logits chunk (independent LDGs, evict-first).
        if (kc + 1 < NCHUNK) {
            #pragma unroll
            for (int j = 0; j < 4; j++)
                nxt[j] = __ldcs(&src4[rb4 + (size_t)(kc + 1) * 16 + q * 4 + j]);
        }

        // exp + rowsum + bf16 store into A[buf] (2 x 16B stores).
        {
            char* a = a_sts + buf * (A_ELEMS * 2);
            uint4 pk0, pk1;
            {
                float e0 = __expf(cur[0].x), e1 = __expf(cur[0].y);
                float e2 = __expf(cur[0].z), e3 = __expf(cur[0].w);
                float e4 = __expf(cur[1].x), e5 = __expf(cur[1].y);
                float e6 = __expf(cur[1].z), e7 = __expf(cur[1].w);
                rs += ((e0 + e1) + (e2 + e3)) + ((e4 + e5) + (e6 + e7));
                __nv_bfloat162 h0 = __floats2bfloat162_rn(e0, e1);
                __nv_bfloat162 h1 = __floats2bfloat162_rn(e2, e3);
                __nv_bfloat162 h2 = __floats2bfloat162_rn(e4, e5);
                __nv_bfloat162 h3 = __floats2bfloat162_rn(e6, e7);
                pk0.x = *(unsigned*)&h0; pk0.y = *(unsigned*)&h1;
                pk0.z = *(unsigned*)&h2; pk0.w = *(unsigned*)&h3;
            }
            {
                float e0 = __expf(cur[2].x), e1 = __expf(cur[2].y);
                float e2 = __expf(cur[2].z), e3 = __expf(cur[2].w);
                float e4 = __expf(cur[3].x), e5 = __expf(cur[3].y);
                float e6 = __expf(cur[3].z), e7 = __expf(cur[3].w);
                rs += ((e0 + e1) + (e2 + e3)) + ((e4 + e5) + (e6 + e7));
                __nv_bfloat162 h0 = __floats2bfloat162_rn(e0, e1);
                __nv_bfloat162 h1 = __floats2bfloat162_rn(e2, e3);
                __nv_bfloat162 h2 = __floats2bfloat162_rn(e4, e5);
                __nv_bfloat162 h3 = __floats2bfloat162_rn(e6, e7);
                pk1.x = *(unsigned*)&h0; pk1.y = *(unsigned*)&h1;
                pk1.z = *(unsigned*)&h2; pk1.w = *(unsigned*)&h3;
            }
            *(uint4*)(a)      = pk0;
            *(uint4*)(a + 16) = pk1;
        }

        // B[kc] must be resident; A[buf] stores visible.
        asm volatile("cp.async.wait_group 0;" ::: "memory");
        __syncthreads();

        // Kick off B chunk kc+1 into the other buffer (its readers are done).
        if (kc + 1 < NCHUNK) {
            uint32_t bdst = b_smem + (buf ^ 1) * (B_ELEMS * 2);
            #pragma unroll
            for (int i = 0; i < 8; i++) {
                int idx = tid + i * NTHREADS;
                int n   = idx >> 3;
                int kv  = idx & 7;
                cp16(bdst + n * ROWB + kv * 16,
                     g_cbT + (size_t)n * VDIM + (kc + 1) * KCH + kv * 8);
            }
            asm volatile("cp.async.commit_group;" ::: "memory");
        }

        // MMA: A[64x64] x B[64x256] with software-pipelined B fragments.
        const uint32_t a_buf = a_smem + buf * (A_ELEMS * 2) + a_lds_off;
        const uint32_t b_buf = b_smem + buf * (B_ELEMS * 2) + b_lds_off;

        #pragma unroll
        for (int ks = 0; ks < 4; ks++) {
            uint32_t afr[2][4];
            uint32_t bfr[2][4];
            ldsm_x4(afr[0], a_buf + ks * 32);
            ldsm_x4(afr[1], a_buf + 16 * ROWB + ks * 32);
            ldsm_x4(bfr[0], b_buf + ks * 32);           // nb = 0
            #pragma unroll
            for (int nb = 0; nb < 4; nb++) {
                const int cu = nb & 1;
                if (nb < 3)
                    ldsm_x4(bfr[cu ^ 1], b_buf + (nb + 1) * 16 * ROWB + ks * 32);
                mma16816(acc[0][nb * 2 + 0], afr[0], bfr[cu][0], bfr[cu][1]);
                mma16816(acc[0][nb * 2 + 1], afr[0], bfr[cu][2], bfr[cu][3]);
                mma16816(acc[1][nb * 2 + 0], afr[1], bfr[cu][0], bfr[cu][1]);
                mma16816(acc[1][nb * 2 + 1], afr[1], bfr[cu][2], bfr[cu][3]);
            }
        }

        #pragma unroll
        for (int j = 0; j < 4; j++) cur[j] = nxt[j];
    }

    // Row-sum reduce across the 4 threads sharing a row.
    {
        float s = rs;
        s += __shfl_xor_sync(0xffffffffu, s, 1);
        s += __shfl_xor_sync(0xffffffffu, s, 2);
        if (q == 0) rowinv[row] = 1.0f / s;
    }
    __syncthreads();

    // Epilogue: pred = acc * rowinv; loss += (pred - cb[target])^2
    const int is64 = g_tgt64;
    const long long* t64 = (const long long*)tgt;
    const int*       t32 = (const int*)tgt;

    float lsum = 0.0f;
    #pragma unroll
    for (int mi = 0; mi < 2; mi++) {
        int lr0 = warp_m * 32 + mi * 16 + (lane >> 2);
        int lr1 = lr0 + 8;
        int r0 = blockIdx.x * M_TILE + lr0;
        int r1 = blockIdx.x * M_TILE + lr1;
        float inv0 = rowinv[lr0];
        float inv1 = rowinv[lr1];
        int tg0 = is64 ? (int)t64[r0] : t32[r0];
        int tg1 = is64 ? (int)t64[r1] : t32[r1];
        const float* cb0 = cb + (size_t)tg0 * DDIM;
        const float* cb1 = cb + (size_t)tg1 * DDIM;
        #pragma unroll
        for (int nf = 0; nf < 8; nf++) {
            int col = warp_n * 64 + nf * 8 + (lane & 3) * 2;
            float2 g0 = *(const float2*)(cb0 + col);
            float2 g1 = *(const float2*)(cb1 + col);
            float d0 = acc[mi][nf][0] * inv0 - g0.x;
            float d1 = acc[mi][nf][1] * inv0 - g0.y;
            float d2 = acc[mi][nf][2] * inv1 - g1.x;
            float d3 = acc[mi][nf][3] * inv1 - g1.y;
            lsum += d0 * d0 + d1 * d1 + d2 * d2 + d3 * d3;
        }
    }
    #pragma unroll
    for (int off = 16; off > 0; off >>= 1)
        lsum += __shfl_xor_sync(0xffffffffu, lsum, off);

    if (lane == 0) sred[wid] = lsum;
    __syncthreads();
    if (tid == 0) {
        float tot = 0.0f;
        #pragma unroll
        for (int i = 0; i < 8; i++) tot += sred[i];
        atomicAdd(out, tot * (1.0f / ((float)NROWS * (float)DDIM)));
    }
}

// ---------------------------------------------------------------------------
// Launch
// ---------------------------------------------------------------------------
extern "C" void kernel_launch(void* const* d_in, const int* in_sizes, int n_in,
                              void* d_out, int out_size) {
    const float* logits = nullptr;
    const void*  tgt    = nullptr;
    const float* cb     = nullptr;
    for (int i = 0; i < n_in; i++) {
        if (in_sizes[i] == NROWS * VDIM)      logits = (const float*)d_in[i];
        else if (in_sizes[i] == NROWS)        tgt    = d_in[i];
        else if (in_sizes[i] == VDIM * DDIM)  cb     = (const float*)d_in[i];
    }
    float* out = (float*)d_out;

    cudaFuncSetAttribute(loss_kernel,
                         cudaFuncAttributeMaxDynamicSharedMemorySize, SMEM_BYTES);

    dim3 pgrid(VDIM / 32, DDIM / 32);
    dim3 pblk(32, 8);
    prep_kernel<<<pgrid, pblk>>>(cb, tgt, out);

    loss_kernel<<<NCTAS, NTHREADS, SMEM_BYTES>>>(logits, tgt, cb, out);
}

// round 10
// speedup vs baseline: 1.6084x; 1.0695x over previous
#include <cuda_runtime.h>
#include <cuda_bf16.h>
#include <cstdint>
#include <cstddef>

// Problem constants
#define NROWS   65536
#define VDIM    1024
#define DDIM    256
#define M_TILE  64
#define NCTAS   (NROWS / M_TILE)     // 1024
#define NTHREADS 256
#define KCH     64
#define NCHUNK  (VDIM / KCH)         // 16
#define ASTRIDE 72                   // bf16 elems per A smem row (144B, conflict-free)
#define BSTRIDE 72
#define A_ELEMS (M_TILE * ASTRIDE)   // 64*72
#define B_ELEMS (DDIM * BSTRIDE)     // 256*72
#define SMEM_BYTES ((2 * A_ELEMS + 2 * B_ELEMS) * 2)   // 92160 B -> 2 CTAs/SM
#define ROWB    (ASTRIDE * 2)        // 144 bytes

// Static scratch: codebook transposed+converted to bf16, [D][V]
__device__ __nv_bfloat16 g_cbT[DDIM * VDIM];
__device__ int g_tgt64;

// ---------------------------------------------------------------------------
// Prep: transpose codebook fp32 [V][D] -> bf16 [D][V]; zero out; dtype sniff.
// ---------------------------------------------------------------------------
__global__ void prep_kernel(const float* __restrict__ cb,
                            const void*  __restrict__ tgt,
                            float* __restrict__ out) {
    __shared__ float tile[32][33];
    int v0 = blockIdx.x * 32;
    int d0 = blockIdx.y * 32;
    int tx = threadIdx.x, ty = threadIdx.y;

    #pragma unroll
    for (int i = 0; i < 4; i++) {
        int v = ty + i * 8;
        tile[v][tx] = cb[(size_t)(v0 + v) * DDIM + d0 + tx];
    }
    __syncthreads();
    #pragma unroll
    for (int i = 0; i < 4; i++) {
        int d = ty + i * 8;
        g_cbT[(size_t)(d0 + d) * VDIM + v0 + tx] = __float2bfloat16(tile[tx][d]);
    }

    if (blockIdx.x == 0 && blockIdx.y == 0 && tx == 0 && ty == 0) {
        const int* t = (const int*)tgt;
        int is64 = 1;
        for (int i = 0; i < 256; i++) {
            if (t[2 * i + 1] != 0) { is64 = 0; break; }
        }
        g_tgt64 = is64;
        out[0] = 0.0f;
    }
}

// ---------------------------------------------------------------------------
// Helpers
// ---------------------------------------------------------------------------
__device__ __forceinline__ uint32_t smem_u32(const void* p) {
    uint32_t a;
    asm("{ .reg .u64 t; cvta.to.shared.u64 t, %1; cvt.u32.u64 %0, t; }" : "=r"(a) : "l"(p));
    return a;
}

__device__ __forceinline__ void cp16(uint32_t dst_smem, const void* src_gmem) {
    asm volatile("cp.async.cg.shared.global [%0], [%1], 16;" :: "r"(dst_smem), "l"(src_gmem));
}

__device__ __forceinline__ void ldsm_x4(uint32_t (&r)[4], uint32_t addr) {
    asm volatile("ldmatrix.sync.aligned.m8n8.x4.shared.b16 {%0,%1,%2,%3}, [%4];"
                 : "=r"(r[0]), "=r"(r[1]), "=r"(r[2]), "=r"(r[3]) : "r"(addr));
}

__device__ __forceinline__ void mma16816(float (&c)[4], const uint32_t (&a)[4],
                                         uint32_t b0, uint32_t b1) {
    asm volatile(
        "mma.sync.aligned.m16n8k16.row.col.f32.bf16.bf16.f32 "
        "{%0,%1,%2,%3}, {%4,%5,%6,%7}, {%8,%9}, {%0,%1,%2,%3};"
        : "+f"(c[0]), "+f"(c[1]), "+f"(c[2]), "+f"(c[3])
        : "r"(a[0]), "r"(a[1]), "r"(a[2]), "r"(a[3]), "r"(b0), "r"(b1));
}

// ---------------------------------------------------------------------------
// Fused streaming kernel (R9 base + exp moved across the barrier):
// per chunk kc: wait B(kc) -> bar -> cp.async B(kc+1) -> exp(kc+1)->A[nbuf]
// -> LDG(kc+2) prefetch -> MMA(kc).
// Grid: 1024 CTAs x 256 threads (8 warps, 2M x 4N). 2 CTAs per SM.
// ---------------------------------------------------------------------------
__global__ void __launch_bounds__(NTHREADS, 2)
loss_kernel(const float* __restrict__ logits,
            const void*  __restrict__ tgt,
            const float* __restrict__ cb,
            float* __restrict__ out) {
    extern __shared__ char smem[];
    char* Ash = smem;                      // 2 x [64][144B]
    char* Bsh = smem + 2 * A_ELEMS * 2;    // 2 x [256][144B]
    __shared__ float rowinv[M_TILE];
    __shared__ float sred[8];

    const int tid  = threadIdx.x;
    const int lane = tid & 31;
    const int wid  = tid >> 5;
    const int warp_m = wid & 1;    // 0..1
    const int warp_n = wid >> 1;   // 0..3

    // Per-thread logits slice: row = tid>>2 (0..63), quarter q = tid&3.
    const int row = tid >> 2;
    const int q   = tid & 3;
    const float4* src4 = (const float4*)(logits + (size_t)blockIdx.x * M_TILE * VDIM);
    const size_t rb4 = (size_t)row * (VDIM / 4);

    const uint32_t a_smem = smem_u32(Ash);
    const uint32_t b_smem = smem_u32(Bsh);

    // ldmatrix source addresses (within a buffer)
    const uint32_t a_lds_off =
        (uint32_t)((warp_m * 32 + (lane & 15)) * ROWB + ((lane >> 4) << 4));
    const uint32_t b_lds_off =
        (uint32_t)((warp_n * 64 + (lane & 7) + ((lane >> 4) << 3)) * ROWB +
                   (((lane >> 3) & 1) << 4));

    // A store target for this thread (within a buffer): 2 x 16B
    char* const a_sts = Ash + row * ROWB + q * 32;

    float rs = 0.0f;

    // exp + pack 16 values from cur into 2 x uint4 and accumulate rowsum
    auto exp_pack = [&rs](const float4* c, uint4& pk0, uint4& pk1) {
        {
            float e0 = __expf(c[0].x), e1 = __expf(c[0].y);
            float e2 = __expf(c[0].z), e3 = __expf(c[0].w);
            float e4 = __expf(c[1].x), e5 = __expf(c[1].y);
            float e6 = __expf(c[1].z), e7 = __expf(c[1].w);
            rs += ((e0 + e1) + (e2 + e3)) + ((e4 + e5) + (e6 + e7));
            __nv_bfloat162 h0 = __floats2bfloat162_rn(e0, e1);
            __nv_bfloat162 h1 = __floats2bfloat162_rn(e2, e3);
            __nv_bfloat162 h2 = __floats2bfloat162_rn(e4, e5);
            __nv_bfloat162 h3 = __floats2bfloat162_rn(e6, e7);
            pk0.x = *(unsigned*)&h0; pk0.y = *(unsigned*)&h1;
            pk0.z = *(unsigned*)&h2; pk0.w = *(unsigned*)&h3;
        }
        {
            float e0 = __expf(c[2].x), e1 = __expf(c[2].y);
            float e2 = __expf(c[2].z), e3 = __expf(c[2].w);
            float e4 = __expf(c[3].x), e5 = __expf(c[3].y);
            float e6 = __expf(c[3].z), e7 = __expf(c[3].w);
            rs += ((e0 + e1) + (e2 + e3)) + ((e4 + e5) + (e6 + e7));
            __nv_bfloat162 h0 = __floats2bfloat162_rn(e0, e1);
            __nv_bfloat162 h1 = __floats2bfloat162_rn(e2, e3);
            __nv_bfloat162 h2 = __floats2bfloat162_rn(e4, e5);
            __nv_bfloat162 h3 = __floats2bfloat162_rn(e6, e7);
            pk1.x = *(unsigned*)&h0; pk1.y = *(unsigned*)&h1;
            pk1.z = *(unsigned*)&h2; pk1.w = *(unsigned*)&h3;
        }
    };

    // --- Prologue ----------------------------------------------------------
    // Issue B chunk 0 copy.
    #pragma unroll
    for (int i = 0; i < 8; i++) {
        int idx = tid + i * NTHREADS;     // 0..2047
        int n   = idx >> 3;
        int kv  = idx & 7;
        cp16(b_smem + n * ROWB + kv * 16, g_cbT + (size_t)n * VDIM + kv * 8);
    }
    asm volatile("cp.async.commit_group;" ::: "memory");

    // Load chunk 0, exp -> A[0]; then load chunk 1 into cur.
    float4 cur[4], nxt[4];
    #pragma unroll
    for (int j = 0; j < 4; j++) cur[j] = __ldcs(&src4[rb4 + q * 4 + j]);
    {
        uint4 pk0, pk1;
        exp_pack(cur, pk0, pk1);
        *(uint4*)(a_sts)      = pk0;
        *(uint4*)(a_sts + 16) = pk1;
    }
    #pragma unroll
    for (int j = 0; j < 4; j++) cur[j] = __ldcs(&src4[rb4 + 16 + q * 4 + j]);

    float acc[2][8][4];
    #pragma unroll
    for (int mi = 0; mi < 2; mi++)
        #pragma unroll
        for (int nf = 0; nf < 8; nf++)
            #pragma unroll
            for (int x = 0; x < 4; x++) acc[mi][nf][x] = 0.0f;

    // --- Main loop ----------------------------------------------------------
    #pragma unroll 1
    for (int kc = 0; kc < NCHUNK; kc++) {
        const int buf = kc & 1;
        const int nbuf = buf ^ 1;

        // B(kc) resident; A[buf] stores (written last window) visible.
        asm volatile("cp.async.wait_group 0;" ::: "memory");
        __syncthreads();

        // Issue B chunk kc+1 into the other buffer (its readers are done).
        if (kc + 1 < NCHUNK) {
            uint32_t bdst = b_smem + nbuf * (B_ELEMS * 2);
            #pragma unroll
            for (int i = 0; i < 8; i++) {
                int idx = tid + i * NTHREADS;
                int n   = idx >> 3;
                int kv  = idx & 7;
                cp16(bdst + n * ROWB + kv * 16,
                     g_cbT + (size_t)n * VDIM + (kc + 1) * KCH + kv * 8);
            }
            asm volatile("cp.async.commit_group;" ::: "memory");
        }

        // exp(kc+1) -> A[nbuf] (no reader until after next barrier).
        if (kc + 1 < NCHUNK) {
            uint4 pk0, pk1;
            exp_pack(cur, pk0, pk1);
            char* a = a_sts + nbuf * (A_ELEMS * 2);
            *(uint4*)(a)      = pk0;
            *(uint4*)(a + 16) = pk1;
        }

        // Prefetch logits chunk kc+2 (contiguous MLP-4 block; covered by MMA).
        if (kc + 2 < NCHUNK) {
            #pragma unroll
            for (int j = 0; j < 4; j++)
                nxt[j] = __ldcs(&src4[rb4 + (size_t)(kc + 2) * 16 + q * 4 + j]);
        }

        // MMA(kc): A[64x64] x B[64x256] with software-pipelined B fragments.
        const uint32_t a_buf = a_smem + buf * (A_ELEMS * 2) + a_lds_off;
        const uint32_t b_buf = b_smem + buf * (B_ELEMS * 2) + b_lds_off;

        #pragma unroll
        for (int ks = 0; ks < 4; ks++) {
            uint32_t afr[2][4];
            uint32_t bfr[2][4];
            ldsm_x4(afr[0], a_buf + ks * 32);
            ldsm_x4(afr[1], a_buf + 16 * ROWB + ks * 32);
            ldsm_x4(bfr[0], b_buf + ks * 32);           // nb = 0
            #pragma unroll
            for (int nb = 0; nb < 4; nb++) {
                const int cu = nb & 1;
                if (nb < 3)
                    ldsm_x4(bfr[cu ^ 1], b_buf + (nb + 1) * 16 * ROWB + ks * 32);
                mma16816(acc[0][nb * 2 + 0], afr[0], bfr[cu][0], bfr[cu][1]);
                mma16816(acc[0][nb * 2 + 1], afr[0], bfr[cu][2], bfr[cu][3]);
                mma16816(acc[1][nb * 2 + 0], afr[1], bfr[cu][0], bfr[cu][1]);
                mma16816(acc[1][nb * 2 + 1], afr[1], bfr[cu][2], bfr[cu][3]);
            }
        }

        #pragma unroll
        for (int j = 0; j < 4; j++) cur[j] = nxt[j];
    }

    // Row-sum reduce across the 4 threads sharing a row.
    {
        float s = rs;
        s += __shfl_xor_sync(0xffffffffu, s, 1);
        s += __shfl_xor_sync(0xffffffffu, s, 2);
        if (q == 0) rowinv[row] = 1.0f / s;
    }
    __syncthreads();

    // Epilogue: pred = acc * rowinv; loss += (pred - cb[target])^2
    const int is64 = g_tgt64;
    const long long* t64 = (const long long*)tgt;
    const int*       t32 = (const int*)tgt;

    float lsum = 0.0f;
    #pragma unroll
    for (int mi = 0; mi < 2; mi++) {
        int lr0 = warp_m * 32 + mi * 16 + (lane >> 2);
        int lr1 = lr0 + 8;
        int r0 = blockIdx.x * M_TILE + lr0;
        int r1 = blockIdx.x * M_TILE + lr1;
        float inv0 = rowinv[lr0];
        float inv1 = rowinv[lr1];
        int tg0 = is64 ? (int)t64[r0] : t32[r0];
        int tg1 = is64 ? (int)t64[r1] : t32[r1];
        const float* cb0 = cb + (size_t)tg0 * DDIM;
        const float* cb1 = cb + (size_t)tg1 * DDIM;
        #pragma unroll
        for (int nf = 0; nf < 8; nf++) {
            int col = warp_n * 64 + nf * 8 + (lane & 3) * 2;
            float2 g0 = *(const float2*)(cb0 + col);
            float2 g1 = *(const float2*)(cb1 + col);
            float d0 = acc[mi][nf][0] * inv0 - g0.x;
            float d1 = acc[mi][nf][1] * inv0 - g0.y;
            float d2 = acc[mi][nf][2] * inv1 - g1.x;
            float d3 = acc[mi][nf][3] * inv1 - g1.y;
            lsum += d0 * d0 + d1 * d1 + d2 * d2 + d3 * d3;
        }
    }
    #pragma unroll
    for (int off = 16; off > 0; off >>= 1)
        lsum += __shfl_xor_sync(0xffffffffu, lsum, off);

    if (lane == 0) sred[wid] = lsum;
    __syncthreads();
    if (tid == 0) {
        float tot = 0.0f;
        #pragma unroll
        for (int i = 0; i < 8; i++) tot += sred[i];
        atomicAdd(out, tot * (1.0f / ((float)NROWS * (float)DDIM)));
    }
}

// ---------------------------------------------------------------------------
// Launch
// ---------------------------------------------------------------------------
extern "C" void kernel_launch(void* const* d_in, const int* in_sizes, int n_in,
                              void* d_out, int out_size) {
    const float* logits = nullptr;
    const void*  tgt    = nullptr;
    const float* cb     = nullptr;
    for (int i = 0; i < n_in; i++) {
        if (in_sizes[i] == NROWS * VDIM)      logits = (const float*)d_in[i];
        else if (in_sizes[i] == NROWS)        tgt    = d_in[i];
        else if (in_sizes[i] == VDIM * DDIM)  cb     = (const float*)d_in[i];
    }
    float* out = (float*)d_out;

    cudaFuncSetAttribute(loss_kernel,
                         cudaFuncAttributeMaxDynamicSharedMemorySize, SMEM_BYTES);

    dim3 pgrid(VDIM / 32, DDIM / 32);
    dim3 pblk(32, 8);
    prep_kernel<<<pgrid, pblk>>>(cb, tgt, out);

    loss_kernel<<<NCTAS, NTHREADS, SMEM_BYTES>>>(logits, tgt, cb, out);
}